// round 10
// baseline (speedup 1.0000x reference)
#include <cuda_runtime.h>
#include <math.h>

// Problem constants
#define U_    128          // LSTM units
#define NG    512          // 4*U (gate width)
#define T_    512          // timesteps
#define B_    256          // batch
#define F_    64           // input features
#define OUT_  6            // dense head

// Fused-gate R split: 88 k-values in SMEM (padded row 92), 40 in regs x 4 columns
#define KSM   88
#define KPAD  92           // 368B row stride: 4-addr phases hit banks {0,28,24,20} -> conflict-free
#define KRG   40
#define NQ_SM (KSM / 4)    // 22
#define NQ_RG (KRG / 4)    // 10

typedef unsigned long long ull;

#define FMA2U(acc, a, b) \
    asm("fma.rn.f32x2 %0, %1, %2, %0;" : "+l"(acc) : "l"(a), "l"(b))

__device__ __forceinline__ ull dup2(float x) {
    ull r;
    asm("mov.b64 %0, {%1, %1};" : "=l"(r) : "f"(x));
    return r;
}
__device__ __forceinline__ float lo32(ull v) { return __int_as_float((int)(v & 0xffffffffull)); }
__device__ __forceinline__ float hi32(ull v) { return __int_as_float((int)(v >> 32)); }
__device__ __forceinline__ float unpack_sum(ull v) { return lo32(v) + hi32(v); }

__device__ __forceinline__ float fast_sigmoid(float x) {
    return __fdividef(1.f, 1.f + __expf(-x));
}
__device__ __forceinline__ float fast_tanh(float x) {
    float e = __expf(fminf(-2.f * x, 80.f));
    return __fdividef(1.f - e, 1.f + e);
}

// ---------------- scratch ----------------
__device__ float g_xw[(size_t)B_ * T_ * NG];
__device__ float g_h [(size_t)B_ * T_ * U_];
__device__ float g_RT[3][NG * U_];
__device__ int   g_nop_sink;

// ---------------- R transpose ----------------
__global__ void k_transpose_R(const float* __restrict__ R, int layer) {
    int j = blockIdx.x;
    int k = threadIdx.x;
    g_RT[layer][j * U_ + k] = R[k * NG + j];
}

// no-op: keeps ncu's fixed capture index (-s 5) on k_lstm
__global__ void k_nop() { if (threadIdx.x == 1024) g_nop_sink = 1; }

// ---------------- GEMM (unchanged) ----------------
#define GBM 128
#define GBN 128
#define GBK 8
#define GPAD 4
__global__ __launch_bounds__(256) void k_gemm_xw(const float* __restrict__ Ain,
                                                 const float* __restrict__ W,
                                                 const float* __restrict__ bias,
                                                 int K) {
    const float* A = Ain ? Ain : g_h;
    __shared__ float As[GBK][GBM + GPAD];
    __shared__ float Bs[GBK][GBN + GPAD];
    const int brow = blockIdx.y * GBM;
    const int bcol = blockIdx.x * GBN;
    const int tid = threadIdx.x;
    const int tx = tid & 15;
    const int ty = tid >> 4;

    const int a_m  = tid >> 1;
    const int a_kq = (tid & 1) * 4;
    const int b_k  = tid >> 5;
    const int b_n  = (tid & 31) * 4;

    ull acc2[8][4];
    #pragma unroll
    for (int i = 0; i < 8; i++)
        #pragma unroll
        for (int j = 0; j < 4; j++) acc2[i][j] = 0ull;

    for (int k0 = 0; k0 < K; k0 += GBK) {
        float4 av = *reinterpret_cast<const float4*>(&A[(size_t)(brow + a_m) * K + (k0 + a_kq)]);
        As[a_kq + 0][a_m] = av.x;
        As[a_kq + 1][a_m] = av.y;
        As[a_kq + 2][a_m] = av.z;
        As[a_kq + 3][a_m] = av.w;
        *reinterpret_cast<float4*>(&Bs[b_k][b_n]) =
            *reinterpret_cast<const float4*>(&W[(size_t)(k0 + b_k) * NG + (bcol + b_n)]);
        __syncthreads();

        #pragma unroll
        for (int k = 0; k < GBK; k++) {
            float4 a0 = *reinterpret_cast<const float4*>(&As[k][ty * 8]);
            float4 a1 = *reinterpret_cast<const float4*>(&As[k][ty * 8 + 4]);
            ulonglong2 bv0 = *reinterpret_cast<const ulonglong2*>(&Bs[k][tx * 8]);
            ulonglong2 bv1 = *reinterpret_cast<const ulonglong2*>(&Bs[k][tx * 8 + 4]);
            ull ad;
            ad = dup2(a0.x);
            FMA2U(acc2[0][0], ad, bv0.x); FMA2U(acc2[0][1], ad, bv0.y);
            FMA2U(acc2[0][2], ad, bv1.x); FMA2U(acc2[0][3], ad, bv1.y);
            ad = dup2(a0.y);
            FMA2U(acc2[1][0], ad, bv0.x); FMA2U(acc2[1][1], ad, bv0.y);
            FMA2U(acc2[1][2], ad, bv1.x); FMA2U(acc2[1][3], ad, bv1.y);
            ad = dup2(a0.z);
            FMA2U(acc2[2][0], ad, bv0.x); FMA2U(acc2[2][1], ad, bv0.y);
            FMA2U(acc2[2][2], ad, bv1.x); FMA2U(acc2[2][3], ad, bv1.y);
            ad = dup2(a0.w);
            FMA2U(acc2[3][0], ad, bv0.x); FMA2U(acc2[3][1], ad, bv0.y);
            FMA2U(acc2[3][2], ad, bv1.x); FMA2U(acc2[3][3], ad, bv1.y);
            ad = dup2(a1.x);
            FMA2U(acc2[4][0], ad, bv0.x); FMA2U(acc2[4][1], ad, bv0.y);
            FMA2U(acc2[4][2], ad, bv1.x); FMA2U(acc2[4][3], ad, bv1.y);
            ad = dup2(a1.y);
            FMA2U(acc2[5][0], ad, bv0.x); FMA2U(acc2[5][1], ad, bv0.y);
            FMA2U(acc2[5][2], ad, bv1.x); FMA2U(acc2[5][3], ad, bv1.y);
            ad = dup2(a1.z);
            FMA2U(acc2[6][0], ad, bv0.x); FMA2U(acc2[6][1], ad, bv0.y);
            FMA2U(acc2[6][2], ad, bv1.x); FMA2U(acc2[6][3], ad, bv1.y);
            ad = dup2(a1.w);
            FMA2U(acc2[7][0], ad, bv0.x); FMA2U(acc2[7][1], ad, bv0.y);
            FMA2U(acc2[7][2], ad, bv1.x); FMA2U(acc2[7][3], ad, bv1.y);
        }
        __syncthreads();
    }

    const int col0 = bcol + tx * 8;
    float bb[8];
    #pragma unroll
    for (int j = 0; j < 8; j++) bb[j] = bias[col0 + j];
    #pragma unroll
    for (int i = 0; i < 8; i++) {
        size_t row = (size_t)(brow + ty * 8 + i);
        float4 o0, o1;
        o0.x = lo32(acc2[i][0]) + bb[0]; o0.y = hi32(acc2[i][0]) + bb[1];
        o0.z = lo32(acc2[i][1]) + bb[2]; o0.w = hi32(acc2[i][1]) + bb[3];
        o1.x = lo32(acc2[i][2]) + bb[4]; o1.y = hi32(acc2[i][2]) + bb[5];
        o1.z = lo32(acc2[i][3]) + bb[6]; o1.w = hi32(acc2[i][3]) + bb[7];
        *reinterpret_cast<float4*>(&g_xw[row * NG + col0])     = o0;
        *reinterpret_cast<float4*>(&g_xw[row * NG + col0 + 4]) = o1;
    }
}

// ---------------- LSTM scan: fused gates, 256 threads, (u,r) = (tid>>1, tid&1) ----------------
// Thread owns all 4 gate columns of unit u for batch row r. Lane pairs (2m,2m+1) read
// identical R addresses -> crossbar broadcast-dedup: each LDS.128 = 2 wavefronts.
// Cell update thread-local (c in register); ping-pong h -> ONE barrier per step.
#define LSTM_SMEM_FLOATS (NG * KPAD + 2 * 2 * U_)
#define LSTM_SMEM_BYTES  (LSTM_SMEM_FLOATS * 4)

__global__ __launch_bounds__(256, 1) void k_lstm(int layer) {
    extern __shared__ float smem[];
    float* sR = smem;                          // [512][KPAD]
    float* sh = sR + NG * KPAD;                // ping-pong [2][2*U_]

    const int tid = threadIdx.x;               // 0..255
    const int u = tid >> 1;                    // unit 0..127
    const int r = tid & 1;                     // batch row within CTA pair
    const int b0 = blockIdx.x * 2;
    const float* RT = g_RT[layer];

    // SMEM R: first KSM k-values of all 512 columns (padded rows)
    for (int i = tid; i < NG * KSM; i += 256) {
        int col = i / KSM, k = i - col * KSM;
        sR[col * KPAD + k] = RT[col * U_ + k];
    }
    // register R tails: 4 gate columns x KRG floats (pairs 2*NQ_SM..63)
    ull rr[4][NQ_RG * 2];
    #pragma unroll
    for (int g = 0; g < 4; g++) {
        const ulonglong2* rg = reinterpret_cast<const ulonglong2*>(RT + (g * U_ + u) * U_ + KSM);
        #pragma unroll
        for (int q = 0; q < NQ_RG; q++) {
            ulonglong2 v = rg[q];
            rr[g][2 * q] = v.x; rr[g][2 * q + 1] = v.y;
        }
    }
    sh[tid] = 0.f;                             // zero h buffer 0 (exactly 256 floats)
    __syncthreads();

    const ulonglong2* rs0 = reinterpret_cast<const ulonglong2*>(sR + (0 * U_ + u) * KPAD);
    const ulonglong2* rs1 = reinterpret_cast<const ulonglong2*>(sR + (1 * U_ + u) * KPAD);
    const ulonglong2* rs2 = reinterpret_cast<const ulonglong2*>(sR + (2 * U_ + u) * KPAD);
    const ulonglong2* rs3 = reinterpret_cast<const ulonglong2*>(sR + (3 * U_ + u) * KPAD);

    const size_t xwbase = (size_t)(b0 + r) * T_ * NG;   // this thread's batch row
    float creg = 0.f;

    float pf[4];
    #pragma unroll
    for (int g = 0; g < 4; g++) pf[g] = __ldcs(&g_xw[xwbase + g * U_ + u]);

    for (int t = 0; t < T_; t++) {
        // h read buffer for this row (broadcast across lane pairs)
        const ulonglong2* hp = reinterpret_cast<const ulonglong2*>(sh + (t & 1) * 2 * U_ + r * U_);
        float* shw = sh + ((t + 1) & 1) * 2 * U_;

        ull ai = (ull)__float_as_uint(pf[0]);
        ull af = (ull)__float_as_uint(pf[1]);
        ull ag = (ull)__float_as_uint(pf[2]);
        ull ao = (ull)__float_as_uint(pf[3]);
        if (t + 1 < T_) {
            size_t o = xwbase + (size_t)(t + 1) * NG;
            #pragma unroll
            for (int g = 0; g < 4; g++) pf[g] = __ldcs(&g_xw[o + g * U_ + u]);
        }

        // SMEM R part: k pairs 0..2*NQ_SM-1
        #pragma unroll
        for (int q = 0; q < NQ_SM; q++) {
            ulonglong2 hv = hp[q];             // h pairs 2q, 2q+1
            ulonglong2 r0 = rs0[q];
            ulonglong2 r1 = rs1[q];
            ulonglong2 r2 = rs2[q];
            ulonglong2 r3 = rs3[q];
            FMA2U(ai, r0.x, hv.x); FMA2U(ai, r0.y, hv.y);
            FMA2U(af, r1.x, hv.x); FMA2U(af, r1.y, hv.y);
            FMA2U(ag, r2.x, hv.x); FMA2U(ag, r2.y, hv.y);
            FMA2U(ao, r3.x, hv.x); FMA2U(ao, r3.y, hv.y);
        }
        // register R part: k pairs 2*NQ_SM..63
        #pragma unroll
        for (int q = 0; q < NQ_RG; q++) {
            ulonglong2 hv = hp[NQ_SM + q];
            FMA2U(ai, rr[0][2 * q], hv.x); FMA2U(ai, rr[0][2 * q + 1], hv.y);
            FMA2U(af, rr[1][2 * q], hv.x); FMA2U(af, rr[1][2 * q + 1], hv.y);
            FMA2U(ag, rr[2][2 * q], hv.x); FMA2U(ag, rr[2][2 * q + 1], hv.y);
            FMA2U(ao, rr[3][2 * q], hv.x); FMA2U(ao, rr[3][2 * q + 1], hv.y);
        }

        // thread-local activations + cell update
        float zi = unpack_sum(ai), zf = unpack_sum(af);
        float zg = unpack_sum(ag), zo = unpack_sum(ao);
        float iv = fast_sigmoid(zi), fv = fast_sigmoid(zf);
        float gv = fast_tanh(zg),    ov = fast_sigmoid(zo);
        creg = fmaf(fv, creg, iv * gv);
        float h = ov * fast_tanh(creg);

        shw[r * U_ + u] = h;
        g_h[((size_t)(b0 + r) * T_ + t) * U_ + u] = h;
        __syncthreads();                        // single barrier per step
    }
}

// ---------------- dense head ----------------
__global__ void k_dense(const float* __restrict__ Wd, const float* __restrict__ bd,
                        float* __restrict__ out) {
    int idx = blockIdx.x * 256 + threadIdx.x;
    if (idx >= B_ * OUT_) return;
    int b = idx / OUT_, j = idx % OUT_;
    const float* hrow = &g_h[((size_t)b * T_ + (T_ - 1)) * U_];
    float s = bd[j];
    #pragma unroll
    for (int k = 0; k < U_; k++) s = fmaf(hrow[k], Wd[k * OUT_ + j], s);
    out[idx] = s;
}

// ---------------- launch ----------------
extern "C" void kernel_launch(void* const* d_in, const int* in_sizes, int n_in,
                              void* d_out, int out_size) {
    const float* x  = (const float*)d_in[0];
    const float* W0 = (const float*)d_in[1];
    const float* R0 = (const float*)d_in[2];
    const float* b0 = (const float*)d_in[3];
    const float* W1 = (const float*)d_in[4];
    const float* R1 = (const float*)d_in[5];
    const float* b1 = (const float*)d_in[6];
    const float* W2 = (const float*)d_in[7];
    const float* R2 = (const float*)d_in[8];
    const float* b2 = (const float*)d_in[9];
    const float* Wd = (const float*)d_in[10];
    const float* bd = (const float*)d_in[11];
    float* out = (float*)d_out;

    cudaFuncSetAttribute(k_lstm, cudaFuncAttributeMaxDynamicSharedMemorySize, LSTM_SMEM_BYTES);

    dim3 gemm_grid(NG / GBN, (B_ * T_) / GBM);

    // launches 0-2: transposes; 3: nop (ncu -s 5 lands on k_lstm); 4: gemm; 5: lstm
    k_transpose_R<<<NG, U_>>>(R0, 0);
    k_transpose_R<<<NG, U_>>>(R1, 1);
    k_transpose_R<<<NG, U_>>>(R2, 2);
    k_nop<<<1, 32>>>();

    k_gemm_xw<<<gemm_grid, 256>>>(x, W0, b0, F_);
    k_lstm<<<B_ / 2, 256, LSTM_SMEM_BYTES>>>(0);

    k_gemm_xw<<<gemm_grid, 256>>>(nullptr, W1, b1, U_);
    k_lstm<<<B_ / 2, 256, LSTM_SMEM_BYTES>>>(1);

    k_gemm_xw<<<gemm_grid, 256>>>(nullptr, W2, b2, U_);
    k_lstm<<<B_ / 2, 256, LSTM_SMEM_BYTES>>>(2);

    k_dense<<<(B_ * OUT_ + 255) / 256, 256>>>(Wd, bd, out);
}

// round 11
// speedup vs baseline: 1.2607x; 1.2607x over previous
#include <cuda_runtime.h>
#include <math.h>

// Problem constants
#define U_    128          // LSTM units
#define NG    512          // 4*U (gate width)
#define T_    512          // timesteps
#define B_    256          // batch
#define F_    64           // input features
#define OUT_  6            // dense head

// R split per gate column: 44 k-values in SMEM, 84 in registers
// stride 44*4=176B; lane 16B-granule offsets 48*l mod 128 cover 8 distinct slots -> conflict-free
#define KSM   44
#define KRG   84
#define NQ_SM (KSM / 4)    // 11  (k pairs 0..21)
#define NQ_RG (KRG / 4)    // 21  (k pairs 22..63)

typedef unsigned long long ull;

#define FMA2U(acc, a, b) \
    asm("fma.rn.f32x2 %0, %1, %2, %0;" : "+l"(acc) : "l"(a), "l"(b))
#define FMA2(acc, a, b) \
    asm("fma.rn.f32x2 %0, %1, %2, %0;" : "+l"(acc) \
        : "l"(__double_as_longlong(a)), "l"(__double_as_longlong(b)))

__device__ __forceinline__ ull dup2(float x) {
    ull r;
    asm("mov.b64 %0, {%1, %1};" : "=l"(r) : "f"(x));
    return r;
}
__device__ __forceinline__ float lo32(ull v) { return __int_as_float((int)(v & 0xffffffffull)); }
__device__ __forceinline__ float hi32(ull v) { return __int_as_float((int)(v >> 32)); }
__device__ __forceinline__ float unpack_sum(ull v) { return lo32(v) + hi32(v); }

__device__ __forceinline__ float fast_sigmoid(float x) {
    return __fdividef(1.f, 1.f + __expf(-x));
}
__device__ __forceinline__ float fast_tanh(float x) {
    float e = __expf(fminf(-2.f * x, 80.f));
    return __fdividef(1.f - e, 1.f + e);
}

// ---------------- scratch ----------------
__device__ float g_xw[(size_t)B_ * T_ * NG];
__device__ float g_h [(size_t)B_ * T_ * U_];
__device__ float g_RT[3][NG * U_];

// ---------------- R transpose ----------------
__global__ void k_transpose_R(const float* __restrict__ R, int layer) {
    int j = blockIdx.x;
    int k = threadIdx.x;
    g_RT[layer][j * U_ + k] = R[k * NG + j];
}

// ---------------- GEMM (unchanged) ----------------
#define GBM 128
#define GBN 128
#define GBK 8
#define GPAD 4
__global__ __launch_bounds__(256) void k_gemm_xw(const float* __restrict__ Ain,
                                                 const float* __restrict__ W,
                                                 const float* __restrict__ bias,
                                                 int K) {
    const float* A = Ain ? Ain : g_h;
    __shared__ float As[GBK][GBM + GPAD];
    __shared__ float Bs[GBK][GBN + GPAD];
    const int brow = blockIdx.y * GBM;
    const int bcol = blockIdx.x * GBN;
    const int tid = threadIdx.x;
    const int tx = tid & 15;
    const int ty = tid >> 4;

    const int a_m  = tid >> 1;
    const int a_kq = (tid & 1) * 4;
    const int b_k  = tid >> 5;
    const int b_n  = (tid & 31) * 4;

    ull acc2[8][4];
    #pragma unroll
    for (int i = 0; i < 8; i++)
        #pragma unroll
        for (int j = 0; j < 4; j++) acc2[i][j] = 0ull;

    for (int k0 = 0; k0 < K; k0 += GBK) {
        float4 av = *reinterpret_cast<const float4*>(&A[(size_t)(brow + a_m) * K + (k0 + a_kq)]);
        As[a_kq + 0][a_m] = av.x;
        As[a_kq + 1][a_m] = av.y;
        As[a_kq + 2][a_m] = av.z;
        As[a_kq + 3][a_m] = av.w;
        *reinterpret_cast<float4*>(&Bs[b_k][b_n]) =
            *reinterpret_cast<const float4*>(&W[(size_t)(k0 + b_k) * NG + (bcol + b_n)]);
        __syncthreads();

        #pragma unroll
        for (int k = 0; k < GBK; k++) {
            float4 a0 = *reinterpret_cast<const float4*>(&As[k][ty * 8]);
            float4 a1 = *reinterpret_cast<const float4*>(&As[k][ty * 8 + 4]);
            ulonglong2 bv0 = *reinterpret_cast<const ulonglong2*>(&Bs[k][tx * 8]);
            ulonglong2 bv1 = *reinterpret_cast<const ulonglong2*>(&Bs[k][tx * 8 + 4]);
            ull ad;
            ad = dup2(a0.x);
            FMA2U(acc2[0][0], ad, bv0.x); FMA2U(acc2[0][1], ad, bv0.y);
            FMA2U(acc2[0][2], ad, bv1.x); FMA2U(acc2[0][3], ad, bv1.y);
            ad = dup2(a0.y);
            FMA2U(acc2[1][0], ad, bv0.x); FMA2U(acc2[1][1], ad, bv0.y);
            FMA2U(acc2[1][2], ad, bv1.x); FMA2U(acc2[1][3], ad, bv1.y);
            ad = dup2(a0.z);
            FMA2U(acc2[2][0], ad, bv0.x); FMA2U(acc2[2][1], ad, bv0.y);
            FMA2U(acc2[2][2], ad, bv1.x); FMA2U(acc2[2][3], ad, bv1.y);
            ad = dup2(a0.w);
            FMA2U(acc2[3][0], ad, bv0.x); FMA2U(acc2[3][1], ad, bv0.y);
            FMA2U(acc2[3][2], ad, bv1.x); FMA2U(acc2[3][3], ad, bv1.y);
            ad = dup2(a1.x);
            FMA2U(acc2[4][0], ad, bv0.x); FMA2U(acc2[4][1], ad, bv0.y);
            FMA2U(acc2[4][2], ad, bv1.x); FMA2U(acc2[4][3], ad, bv1.y);
            ad = dup2(a1.y);
            FMA2U(acc2[5][0], ad, bv0.x); FMA2U(acc2[5][1], ad, bv0.y);
            FMA2U(acc2[5][2], ad, bv1.x); FMA2U(acc2[5][3], ad, bv1.y);
            ad = dup2(a1.z);
            FMA2U(acc2[6][0], ad, bv0.x); FMA2U(acc2[6][1], ad, bv0.y);
            FMA2U(acc2[6][2], ad, bv1.x); FMA2U(acc2[6][3], ad, bv1.y);
            ad = dup2(a1.w);
            FMA2U(acc2[7][0], ad, bv0.x); FMA2U(acc2[7][1], ad, bv0.y);
            FMA2U(acc2[7][2], ad, bv1.x); FMA2U(acc2[7][3], ad, bv1.y);
        }
        __syncthreads();
    }

    const int col0 = bcol + tx * 8;
    float bb[8];
    #pragma unroll
    for (int j = 0; j < 8; j++) bb[j] = bias[col0 + j];
    #pragma unroll
    for (int i = 0; i < 8; i++) {
        size_t row = (size_t)(brow + ty * 8 + i);
        float4 o0, o1;
        o0.x = lo32(acc2[i][0]) + bb[0]; o0.y = hi32(acc2[i][0]) + bb[1];
        o0.z = lo32(acc2[i][1]) + bb[2]; o0.w = hi32(acc2[i][1]) + bb[3];
        o1.x = lo32(acc2[i][2]) + bb[4]; o1.y = hi32(acc2[i][2]) + bb[5];
        o1.z = lo32(acc2[i][3]) + bb[6]; o1.w = hi32(acc2[i][3]) + bb[7];
        *reinterpret_cast<float4*>(&g_xw[row * NG + col0])     = o0;
        *reinterpret_cast<float4*>(&g_xw[row * NG + col0 + 4]) = o1;
    }
}

// ---------------- LSTM scan (R6 layout, KSM=44/KRG=84, SMEM padded >113.5KB) ----------------
#define LSTM_SMEM_FLOATS 30000
#define LSTM_SMEM_BYTES  (LSTM_SMEM_FLOATS * 4)

__global__ __launch_bounds__(256) void k_lstm(int layer) {
    extern __shared__ float smem[];
    float* sR   = smem;                       // [512][KSM]
    float* sh   = sR + NG * KSM;              // [2][128] current h
    float* sc   = sh + 2 * U_;                // [2][128] cell state
    float* sact = sc + 2 * U_;                // [2][512] activated gates

    const int tid = threadIdx.x;              // 0..255
    const int c0 = tid;                       // gate col (i or f)
    const int c1 = tid + 256;                 // gate col (g or o)
    const int b0 = blockIdx.x * 2;
    const float* RT = g_RT[layer];

    for (int i = tid; i < NG * KSM; i += 256) {
        int col = i / KSM, k = i - col * KSM;
        sR[i] = RT[col * U_ + k];
    }
    double rr0[NQ_RG * 2], rr1[NQ_RG * 2];
    {
        const double2* rg0 = reinterpret_cast<const double2*>(RT + c0 * U_ + KSM);
        const double2* rg1 = reinterpret_cast<const double2*>(RT + c1 * U_ + KSM);
        #pragma unroll
        for (int q = 0; q < NQ_RG; q++) {
            double2 v0 = rg0[q];
            double2 v1 = rg1[q];
            rr0[2 * q] = v0.x; rr0[2 * q + 1] = v0.y;
            rr1[2 * q] = v1.x; rr1[2 * q + 1] = v1.y;
        }
    }
    { sh[tid] = 0.f; sc[tid] = 0.f; }
    __syncthreads();

    const double2* rs0 = reinterpret_cast<const double2*>(sR + c0 * KSM);
    const double2* rs1 = reinterpret_cast<const double2*>(sR + c1 * KSM);
    const double2* h0p = reinterpret_cast<const double2*>(sh);
    const double2* h1p = reinterpret_cast<const double2*>(sh + U_);
    const size_t xw0base = (size_t)b0 * T_ * NG;
    const size_t xw1base = (size_t)(b0 + 1) * T_ * NG;

    float pf00 = __ldcs(&g_xw[xw0base + c0]);
    float pf01 = __ldcs(&g_xw[xw0base + c1]);
    float pf10 = __ldcs(&g_xw[xw1base + c0]);
    float pf11 = __ldcs(&g_xw[xw1base + c1]);

    for (int t = 0; t < T_; t++) {
        ull a00 = (ull)__float_as_uint(pf00);
        ull a01 = (ull)__float_as_uint(pf01);
        ull a10 = (ull)__float_as_uint(pf10);
        ull a11 = (ull)__float_as_uint(pf11);
        if (t + 1 < T_) {
            size_t o0 = xw0base + (size_t)(t + 1) * NG;
            size_t o1 = xw1base + (size_t)(t + 1) * NG;
            pf00 = __ldcs(&g_xw[o0 + c0]);
            pf01 = __ldcs(&g_xw[o0 + c1]);
            pf10 = __ldcs(&g_xw[o1 + c0]);
            pf11 = __ldcs(&g_xw[o1 + c1]);
        }

        #pragma unroll
        for (int q = 0; q < NQ_SM; q++) {
            double2 r0 = rs0[q];
            double2 r1 = rs1[q];
            double2 h0 = h0p[q];
            double2 h1 = h1p[q];
            FMA2(a00, r0.x, h0.x); FMA2(a01, r1.x, h0.x);
            FMA2(a10, r0.x, h1.x); FMA2(a11, r1.x, h1.x);
            FMA2(a00, r0.y, h0.y); FMA2(a01, r1.y, h0.y);
            FMA2(a10, r0.y, h1.y); FMA2(a11, r1.y, h1.y);
        }
        #pragma unroll
        for (int q = 0; q < NQ_RG; q++) {
            double2 h0 = h0p[NQ_SM + q];
            double2 h1 = h1p[NQ_SM + q];
            FMA2(a00, rr0[2 * q], h0.x); FMA2(a01, rr1[2 * q], h0.x);
            FMA2(a10, rr0[2 * q], h1.x); FMA2(a11, rr1[2 * q], h1.x);
            FMA2(a00, rr0[2 * q + 1], h0.y); FMA2(a01, rr1[2 * q + 1], h0.y);
            FMA2(a10, rr0[2 * q + 1], h1.y); FMA2(a11, rr1[2 * q + 1], h1.y);
        }

        float z00 = unpack_sum(a00);
        float z01 = unpack_sum(a01);
        float z10 = unpack_sum(a10);
        float z11 = unpack_sum(a11);

        float s00 = fast_sigmoid(z00);        // c0: i or f gate
        float s10 = fast_sigmoid(z10);
        float s01, s11;                       // c1: g (tanh) or o (sigmoid)
        if (tid < 128) { s01 = fast_tanh(z01);    s11 = fast_tanh(z11); }
        else           { s01 = fast_sigmoid(z01); s11 = fast_sigmoid(z11); }

        sact[c0] = s00;        sact[c1] = s01;
        sact[NG + c0] = s10;   sact[NG + c1] = s11;
        __syncthreads();

        {   // cell update: thread owns (m,u)
            int m = tid >> 7, u = tid & (U_ - 1);
            const float* s = sact + m * NG;
            float iv = s[u], fv = s[U_ + u], gv = s[2 * U_ + u], ov = s[3 * U_ + u];
            float c = fmaf(fv, sc[tid], iv * gv);
            float h = ov * fast_tanh(c);
            sc[tid] = c;
            sh[m * U_ + u] = h;
            g_h[((size_t)(b0 + m) * T_ + t) * U_ + u] = h;
        }
        __syncthreads();
    }
}

// ---------------- dense head ----------------
__global__ void k_dense(const float* __restrict__ Wd, const float* __restrict__ bd,
                        float* __restrict__ out) {
    int idx = blockIdx.x * 256 + threadIdx.x;
    if (idx >= B_ * OUT_) return;
    int b = idx / OUT_, j = idx % OUT_;
    const float* hrow = &g_h[((size_t)b * T_ + (T_ - 1)) * U_];
    float s = bd[j];
    #pragma unroll
    for (int k = 0; k < U_; k++) s = fmaf(hrow[k], Wd[k * OUT_ + j], s);
    out[idx] = s;
}

// ---------------- launch ----------------
extern "C" void kernel_launch(void* const* d_in, const int* in_sizes, int n_in,
                              void* d_out, int out_size) {
    const float* x  = (const float*)d_in[0];
    const float* W0 = (const float*)d_in[1];
    const float* R0 = (const float*)d_in[2];
    const float* b0 = (const float*)d_in[3];
    const float* W1 = (const float*)d_in[4];
    const float* R1 = (const float*)d_in[5];
    const float* b1 = (const float*)d_in[6];
    const float* W2 = (const float*)d_in[7];
    const float* R2 = (const float*)d_in[8];
    const float* b2 = (const float*)d_in[9];
    const float* Wd = (const float*)d_in[10];
    const float* bd = (const float*)d_in[11];
    float* out = (float*)d_out;

    cudaFuncSetAttribute(k_lstm, cudaFuncAttributeMaxDynamicSharedMemorySize, LSTM_SMEM_BYTES);

    dim3 gemm_grid(NG / GBN, (B_ * T_) / GBM);

    // Launch order chosen so ncu's effective capture slot (index 3) = k_lstm:
    //   0: t0, 1: gemm0, 2: t1, 3: lstm0, 4: t2, 5: gemm1, 6: lstm1, ...
    k_transpose_R<<<NG, U_>>>(R0, 0);
    k_gemm_xw<<<gemm_grid, 256>>>(x, W0, b0, F_);
    k_transpose_R<<<NG, U_>>>(R1, 1);
    k_lstm<<<B_ / 2, 256, LSTM_SMEM_BYTES>>>(0);
    k_transpose_R<<<NG, U_>>>(R2, 2);

    k_gemm_xw<<<gemm_grid, 256>>>(nullptr, W1, b1, U_);
    k_lstm<<<B_ / 2, 256, LSTM_SMEM_BYTES>>>(1);

    k_gemm_xw<<<gemm_grid, 256>>>(nullptr, W2, b2, U_);
    k_lstm<<<B_ / 2, 256, LSTM_SMEM_BYTES>>>(2);

    k_dense<<<(B_ * OUT_ + 255) / 256, 256>>>(Wd, bd, out);
}